// round 14
// baseline (speedup 1.0000x reference)
#include <cuda_runtime.h>

#define N_NODES 50000
#define N_EDGES 800000
#define D 128
#define NBATCH 64
#define EPW 32                 // edges per warp (800000 = 25000*32), fixed unroll

// ---------------- device scratch (allocation-free) ----------------
__device__ float g_agg[N_NODES * D];      // neighbor sums (re-zeroed by epilogue)
__device__ float g_S[NBATCH * D];         // pooled sums (re-zeroed by k_pool)
__device__ float g_cnt[NBATCH];           // batch counts (re-zeroed by k_pool)
__device__ int   g_deg[N_NODES];          // per-src degree (zeroed by k_setup)
__device__ int   g_cursor[N_NODES];       // fill cursors (set by k_scan)
__device__ int2  g_e2[N_EDGES];           // (src,dst) pairs sorted by src

// ---------------------------------------------------------------------------
// 0) zero per-src degree
// ---------------------------------------------------------------------------
__global__ void k_setup() {
    int i = blockIdx.x * blockDim.x + threadIdx.x;
    if (i < N_NODES) g_deg[i] = 0;
}

// ---------------------------------------------------------------------------
// 1) histogram of src (atomicAdd w/ unused result -> RED)
// ---------------------------------------------------------------------------
__global__ void k_hist(const int* __restrict__ ei) {
    int e = blockIdx.x * blockDim.x + threadIdx.x;
    if (e < N_EDGES) atomicAdd(&g_deg[__ldg(&ei[e])], 1);
}

// ---------------------------------------------------------------------------
// 2) exclusive scan of g_deg -> g_cursor. One 1024-thread block.
// ---------------------------------------------------------------------------
__global__ void k_scan() {
    __shared__ int sums[1024];
    const int CH = (N_NODES + 1023) / 1024;   // 49
    int t = threadIdx.x;
    int beg = t * CH;
    int end = beg + CH; if (end > N_NODES) end = N_NODES;

    int s = 0;
    for (int i = beg; i < end; i++) s += g_deg[i];
    sums[t] = s;
    __syncthreads();
    for (int off = 1; off < 1024; off <<= 1) {
        int v = (t >= off) ? sums[t - off] : 0;
        __syncthreads();
        sums[t] += v;
        __syncthreads();
    }
    int run = (t == 0) ? 0 : sums[t - 1];
    for (int i = beg; i < end; i++) {
        g_cursor[i] = run;
        run += g_deg[i];
    }
}

// ---------------------------------------------------------------------------
// 3) permute into src-sorted (src,dst) pairs
// ---------------------------------------------------------------------------
__global__ void k_fill(const int* __restrict__ ei) {
    int e = blockIdx.x * blockDim.x + threadIdx.x;
    if (e >= N_EDGES) return;
    int src = __ldg(&ei[e]);
    int dst = __ldg(&ei[N_EDGES + e]);
    int p = atomicAdd(&g_cursor[src], 1);
    g_e2[p] = make_int2(src, dst);
}

// ---------------------------------------------------------------------------
// 4) edge scatter over SRC-SORTED edges — exact R7 winning shape (fixed
//    unroll, fire-and-forget vector REDs). Gather uses L1-allocating __ldg:
//    consecutive edges share src, so ~30/32 gathers are L1 hits -> external
//    gather traffic drops from 512B/edge to ~32B/edge.
// ---------------------------------------------------------------------------
__global__ void __launch_bounds__(256) k_edges(const float* __restrict__ x) {
    int warp = (blockIdx.x * blockDim.x + threadIdx.x) >> 5;
    int lane = threadIdx.x & 31;
    long long base = (long long)warp * EPW;
    if (base >= N_EDGES) return;

    int2 e = g_e2[base + lane];        // coalesced 256B pair load
    int src = e.x, dst = e.y;

    const float4* x4 = reinterpret_cast<const float4*>(x);

    #pragma unroll
    for (int j = 0; j < EPW; j++) {
        int s = __shfl_sync(0xffffffffu, src, j);
        int d = __shfl_sync(0xffffffffu, dst, j);
        float4 v = __ldg(&x4[(size_t)s * 32 + lane]);   // L1 hit for repeated src
        float* p = g_agg + (size_t)d * D + lane * 4;
        asm volatile("red.global.add.v4.f32 [%0], {%1, %2, %3, %4};"
                     :: "l"(p), "f"(v.x), "f"(v.y), "f"(v.z), "f"(v.w)
                     : "memory");
    }
}

// ---------------------------------------------------------------------------
// 5) epilogue: out = relu(scale*x + agg), re-zero agg, per-batch pooled sums
//    with run-length compression (batch sorted). One warp per 16 rows.
// ---------------------------------------------------------------------------
#define EPI_ROWS 16

__global__ void __launch_bounds__(256) k_epilogue(const float* __restrict__ x,
                                                  const float* __restrict__ eps,
                                                  const int* __restrict__ batch,
                                                  float* __restrict__ out) {
    int warp = (blockIdx.x * blockDim.x + threadIdx.x) >> 5;
    int lane = threadIdx.x & 31;
    int r0 = warp * EPI_ROWS;
    if (r0 >= N_NODES) return;
    int r1 = r0 + EPI_ROWS; if (r1 > N_NODES) r1 = N_NODES;

    float scale = 1.0f + eps[0];
    float4* agg4 = reinterpret_cast<float4*>(g_agg);
    const float4* x4 = reinterpret_cast<const float4*>(x);
    float4* out4 = reinterpret_cast<float4*>(out);
    const float4 zero4 = make_float4(0.f, 0.f, 0.f, 0.f);

    float4 acc = zero4;
    int cnt = 0;
    int cur = batch[r0];

    for (int r = r0; r < r1; r++) {
        size_t idx = (size_t)r * 32 + lane;
        float4 a  = __ldcg(&agg4[idx]);
        float4 xv = x4[idx];
        float4 v;
        v.x = fmaxf(fmaf(xv.x, scale, a.x), 0.f);
        v.y = fmaxf(fmaf(xv.y, scale, a.y), 0.f);
        v.z = fmaxf(fmaf(xv.z, scale, a.z), 0.f);
        v.w = fmaxf(fmaf(xv.w, scale, a.w), 0.f);
        out4[idx] = v;
        agg4[idx] = zero4;                 // self-restore for next replay

        int b = batch[r];
        if (b != cur) {
            float* p = &g_S[cur * D + lane * 4];
            asm volatile("red.global.add.v4.f32 [%0], {%1, %2, %3, %4};"
                         :: "l"(p), "f"(acc.x), "f"(acc.y), "f"(acc.z), "f"(acc.w)
                         : "memory");
            if (lane == 0) atomicAdd(&g_cnt[cur], (float)cnt);
            cur = b; acc = zero4; cnt = 0;
        }
        acc.x += v.x; acc.y += v.y; acc.z += v.z; acc.w += v.w;
        cnt++;
    }
    {
        float* p = &g_S[cur * D + lane * 4];
        asm volatile("red.global.add.v4.f32 [%0], {%1, %2, %3, %4};"
                     :: "l"(p), "f"(acc.x), "f"(acc.y), "f"(acc.z), "f"(acc.w)
                     : "memory");
        if (lane == 0) atomicAdd(&g_cnt[cur], (float)cnt);
    }
}

// ---------------------------------------------------------------------------
// 6) pooled2[b] = S[b] @ W + cnt[b]*bias. Reads then re-zeroes g_S / g_cnt.
// ---------------------------------------------------------------------------
__global__ void k_pool(const float* __restrict__ W,
                       const float* __restrict__ bias,
                       float* __restrict__ out2) {
    int b = blockIdx.x;     // 0..63
    int j = threadIdx.x;    // 0..127
    __shared__ float s[D];
    __shared__ float cntf;
    s[j] = g_S[b * D + j];
    g_S[b * D + j] = 0.0f;                 // self-restore
    if (j == 0) { cntf = g_cnt[b]; g_cnt[b] = 0.0f; }
    __syncthreads();

    float a0 = 0.f, a1 = 0.f, a2 = 0.f, a3 = 0.f;
    #pragma unroll
    for (int k = 0; k < D; k += 4) {
        a0 = fmaf(s[k + 0], __ldg(&W[(k + 0) * D + j]), a0);
        a1 = fmaf(s[k + 1], __ldg(&W[(k + 1) * D + j]), a1);
        a2 = fmaf(s[k + 2], __ldg(&W[(k + 2) * D + j]), a2);
        a3 = fmaf(s[k + 3], __ldg(&W[(k + 3) * D + j]), a3);
    }
    out2[b * D + j] = cntf * bias[j] + ((a0 + a1) + (a2 + a3));
}

// ---------------------------------------------------------------------------
// launch: x, eps, W_pred, b_pred, edge_index, batch -> out | pooled2
// ---------------------------------------------------------------------------
extern "C" void kernel_launch(void* const* d_in, const int* in_sizes, int n_in,
                              void* d_out, int out_size) {
    const float* x     = (const float*)d_in[0];
    const float* eps   = (const float*)d_in[1];
    const float* Wp    = (const float*)d_in[2];
    const float* bp    = (const float*)d_in[3];
    const int*   ei    = (const int*)d_in[4];
    const int*   batch = (const int*)d_in[5];

    float* out  = (float*)d_out;
    float* out2 = out + (size_t)N_NODES * D;

    k_setup<<<(N_NODES + 255) / 256, 256>>>();
    k_hist <<<(N_EDGES + 255) / 256, 256>>>(ei);
    k_scan <<<1, 1024>>>();
    k_fill <<<(N_EDGES + 255) / 256, 256>>>(ei);

    {
        int warps = (N_EDGES + EPW - 1) / EPW;               // 25000
        int blocks = (warps * 32 + 255) / 256;               // 3125
        k_edges<<<blocks, 256>>>(x);
    }

    {
        int warps = (N_NODES + EPI_ROWS - 1) / EPI_ROWS;     // 3125
        int blocks = (warps * 32 + 255) / 256;               // 391
        k_epilogue<<<blocks, 256>>>(x, eps, batch, out);
    }

    k_pool<<<NBATCH, 128>>>(Wp, bp, out2);
}

// round 15
// speedup vs baseline: 1.6352x; 1.6352x over previous
#include <cuda_runtime.h>
#include <cuda_fp16.h>

#define N_NODES 50000
#define N_EDGES 800000
#define D 128
#define NBATCH 64
#define EPW 16                 // edges per warp (best measured config, R6)

// Device scratch (allocation-free, self-restoring across graph replays).
__device__ float         g_agg[N_NODES * D];   // neighbor sums (re-zeroed by epilogue)
__device__ float         g_S[NBATCH * D];      // pooled sums (re-zeroed by k_pool)
__device__ float         g_cnt[NBATCH];        // batch counts (re-zeroed by k_pool)
__device__ unsigned int  g_xh[N_NODES * D / 2];// x in fp16 (2 halves per uint)

// ---------------------------------------------------------------------------
// 0) convert x -> fp16 copy (read 25.6MB, write 12.8MB; ~4us)
// ---------------------------------------------------------------------------
__global__ void k_convert(const float* __restrict__ x) {
    int i = blockIdx.x * blockDim.x + threadIdx.x;   // one float4 -> 2 half2
    const int total4 = N_NODES * D / 4;
    if (i >= total4) return;
    float4 v = __ldcs(&reinterpret_cast<const float4*>(x)[i]);
    half2 h0 = __floats2half2_rn(v.x, v.y);
    half2 h1 = __floats2half2_rn(v.z, v.w);
    uint2 packed;
    packed.x = *reinterpret_cast<unsigned int*>(&h0);
    packed.y = *reinterpret_cast<unsigned int*>(&h1);
    reinterpret_cast<uint2*>(g_xh)[i] = packed;
}

// ---------------------------------------------------------------------------
// 1) edge scatter: one warp per 16 edges (proven best shape).
//    Lanes 0-15 load srcs, 16-31 load dsts (coalesced), then 16 fully-unrolled
//    independent chains: 8B fp16 gather -> cvt -> fp32 vector RED.
//    Gather bytes: 256/edge (was 512). RED bytes: 512/edge (unchanged, fp32).
// ---------------------------------------------------------------------------
__global__ void __launch_bounds__(256) k_edges(const int* __restrict__ ei) {
    int warp = (blockIdx.x * blockDim.x + threadIdx.x) >> 5;
    int lane = threadIdx.x & 31;
    long long base = (long long)warp * EPW;
    if (base >= N_EDGES) return;

    int idx = (lane < EPW) ? __ldg(&ei[base + lane])
                           : __ldg(&ei[N_EDGES + base + (lane - EPW)]);

    const uint2* xh2 = reinterpret_cast<const uint2*>(g_xh);  // 32 uint2 per row

    #pragma unroll
    for (int j = 0; j < EPW; j++) {
        int s = __shfl_sync(0xffffffffu, idx, j);
        int d = __shfl_sync(0xffffffffu, idx, EPW + j);
        uint2 raw = __ldg(&xh2[(size_t)s * 32 + lane]);       // 4 halves
        half2 h0 = *reinterpret_cast<half2*>(&raw.x);
        half2 h1 = *reinterpret_cast<half2*>(&raw.y);
        float2 f0 = __half22float2(h0);
        float2 f1 = __half22float2(h1);
        float* p = g_agg + (size_t)d * D + lane * 4;
        asm volatile("red.global.add.v4.f32 [%0], {%1, %2, %3, %4};"
                     :: "l"(p), "f"(f0.x), "f"(f0.y), "f"(f1.x), "f"(f1.y)
                     : "memory");
    }
}

// ---------------------------------------------------------------------------
// 2) epilogue: out = relu(scale*x + agg) (x read in full fp32 precision),
//    re-zero agg, per-batch pooled sums with run-length compression.
// ---------------------------------------------------------------------------
#define EPI_ROWS 16

__global__ void __launch_bounds__(256) k_epilogue(const float* __restrict__ x,
                                                  const float* __restrict__ eps,
                                                  const int* __restrict__ batch,
                                                  float* __restrict__ out) {
    int warp = (blockIdx.x * blockDim.x + threadIdx.x) >> 5;
    int lane = threadIdx.x & 31;
    int r0 = warp * EPI_ROWS;
    if (r0 >= N_NODES) return;
    int r1 = r0 + EPI_ROWS; if (r1 > N_NODES) r1 = N_NODES;

    float scale = 1.0f + eps[0];
    float4* agg4 = reinterpret_cast<float4*>(g_agg);
    const float4* x4 = reinterpret_cast<const float4*>(x);
    float4* out4 = reinterpret_cast<float4*>(out);
    const float4 zero4 = make_float4(0.f, 0.f, 0.f, 0.f);

    float4 acc = zero4;
    int cnt = 0;
    int cur = batch[r0];

    for (int r = r0; r < r1; r++) {
        size_t idx = (size_t)r * 32 + lane;
        float4 a  = __ldcg(&agg4[idx]);
        float4 xv = x4[idx];
        float4 v;
        v.x = fmaxf(fmaf(xv.x, scale, a.x), 0.f);
        v.y = fmaxf(fmaf(xv.y, scale, a.y), 0.f);
        v.z = fmaxf(fmaf(xv.z, scale, a.z), 0.f);
        v.w = fmaxf(fmaf(xv.w, scale, a.w), 0.f);
        out4[idx] = v;
        agg4[idx] = zero4;                 // self-restore for next replay

        int b = batch[r];
        if (b != cur) {
            float* p = &g_S[cur * D + lane * 4];
            asm volatile("red.global.add.v4.f32 [%0], {%1, %2, %3, %4};"
                         :: "l"(p), "f"(acc.x), "f"(acc.y), "f"(acc.z), "f"(acc.w)
                         : "memory");
            if (lane == 0) atomicAdd(&g_cnt[cur], (float)cnt);
            cur = b; acc = zero4; cnt = 0;
        }
        acc.x += v.x; acc.y += v.y; acc.z += v.z; acc.w += v.w;
        cnt++;
    }
    {
        float* p = &g_S[cur * D + lane * 4];
        asm volatile("red.global.add.v4.f32 [%0], {%1, %2, %3, %4};"
                     :: "l"(p), "f"(acc.x), "f"(acc.y), "f"(acc.z), "f"(acc.w)
                     : "memory");
        if (lane == 0) atomicAdd(&g_cnt[cur], (float)cnt);
    }
}

// ---------------------------------------------------------------------------
// 3) pooled2[b] = S[b] @ W + cnt[b]*bias. Reads then re-zeroes g_S / g_cnt.
// ---------------------------------------------------------------------------
__global__ void k_pool(const float* __restrict__ W,
                       const float* __restrict__ bias,
                       float* __restrict__ out2) {
    int b = blockIdx.x;     // 0..63
    int j = threadIdx.x;    // 0..127
    __shared__ float s[D];
    __shared__ float cntf;
    s[j] = g_S[b * D + j];
    g_S[b * D + j] = 0.0f;                 // self-restore
    if (j == 0) { cntf = g_cnt[b]; g_cnt[b] = 0.0f; }
    __syncthreads();

    float a0 = 0.f, a1 = 0.f, a2 = 0.f, a3 = 0.f;
    #pragma unroll
    for (int k = 0; k < D; k += 4) {
        a0 = fmaf(s[k + 0], __ldg(&W[(k + 0) * D + j]), a0);
        a1 = fmaf(s[k + 1], __ldg(&W[(k + 1) * D + j]), a1);
        a2 = fmaf(s[k + 2], __ldg(&W[(k + 2) * D + j]), a2);
        a3 = fmaf(s[k + 3], __ldg(&W[(k + 3) * D + j]), a3);
    }
    out2[b * D + j] = cntf * bias[j] + ((a0 + a1) + (a2 + a3));
}

// ---------------------------------------------------------------------------
// launch: x, eps, W_pred, b_pred, edge_index, batch -> out | pooled2
// ---------------------------------------------------------------------------
extern "C" void kernel_launch(void* const* d_in, const int* in_sizes, int n_in,
                              void* d_out, int out_size) {
    const float* x     = (const float*)d_in[0];
    const float* eps   = (const float*)d_in[1];
    const float* Wp    = (const float*)d_in[2];
    const float* bp    = (const float*)d_in[3];
    const int*   ei    = (const int*)d_in[4];
    const int*   batch = (const int*)d_in[5];

    float* out  = (float*)d_out;
    float* out2 = out + (size_t)N_NODES * D;

    // fp16 copy of x
    {
        int total4 = N_NODES * D / 4;
        k_convert<<<(total4 + 255) / 256, 256>>>(x);
    }

    // edge scatter: one warp per EPW edges
    {
        int warps = (N_EDGES + EPW - 1) / EPW;               // 50000
        int blocks = (warps * 32 + 255) / 256;               // 6250
        k_edges<<<blocks, 256>>>(ei);
    }

    // epilogue: relu + out + agg re-zero + batch partial sums
    {
        int warps = (N_NODES + EPI_ROWS - 1) / EPI_ROWS;     // 3125
        int blocks = (warps * 32 + 255) / 256;               // 391
        k_epilogue<<<blocks, 256>>>(x, eps, batch, out);
    }

    // tiny pooled GEMM
    k_pool<<<NBATCH, 128>>>(Wp, bp, out2);
}

// round 16
// speedup vs baseline: 2.5290x; 1.5466x over previous
#include <cuda_runtime.h>
#include <cuda_fp16.h>

#define N_NODES 50000
#define N_EDGES 800000
#define D 128
#define NBATCH 64
#define EPW 16                 // edges per warp (proven best shape)

// Device scratch (allocation-free, self-restoring across graph replays).
__device__ unsigned int g_aggh[N_NODES * D / 2]; // fp16 neighbor sums (re-zeroed by epilogue)
__device__ unsigned int g_xh[N_NODES * D / 2];   // x in fp16
__device__ float        g_S[NBATCH * D];         // pooled sums (re-zeroed by k_pool)
__device__ float        g_cnt[NBATCH];           // batch counts (re-zeroed by k_pool)

// ---------------------------------------------------------------------------
// 0) convert x -> fp16 copy
// ---------------------------------------------------------------------------
__global__ void k_convert(const float* __restrict__ x) {
    int i = blockIdx.x * blockDim.x + threadIdx.x;   // one float4 -> 2 half2
    const int total4 = N_NODES * D / 4;
    if (i >= total4) return;
    float4 v = __ldcs(&reinterpret_cast<const float4*>(x)[i]);
    half2 h0 = __floats2half2_rn(v.x, v.y);
    half2 h1 = __floats2half2_rn(v.z, v.w);
    uint2 packed;
    packed.x = *reinterpret_cast<unsigned int*>(&h0);
    packed.y = *reinterpret_cast<unsigned int*>(&h1);
    reinterpret_cast<uint2*>(g_xh)[i] = packed;
}

// ---------------------------------------------------------------------------
// 1) edge scatter: one warp per 16 edges; TWO edges per iteration (half-warp
//    each), fixed unroll of 8. Gather 16B/lane fp16, then one fire-and-forget
//    red.global.add.noftz.v4.f16x2 (16B = 8 halves) per lane.
//    RED lane-ops: 16/edge (was 32). RED bytes: 256/edge (was 512).
// ---------------------------------------------------------------------------
__global__ void __launch_bounds__(256) k_edges(const int* __restrict__ ei) {
    int warp = (blockIdx.x * blockDim.x + threadIdx.x) >> 5;
    int lane = threadIdx.x & 31;
    long long base = (long long)warp * EPW;
    if (base >= N_EDGES) return;

    // lanes 0-15: srcs of edges 0..15; lanes 16-31: dsts of edges 0..15
    int idx = (lane < EPW) ? __ldg(&ei[base + lane])
                           : __ldg(&ei[N_EDGES + base + (lane - EPW)]);

    const uint4* xh4 = reinterpret_cast<const uint4*>(g_xh);  // 16 uint4 per row
    __half* aggh = reinterpret_cast<__half*>(g_aggh);

    int half = lane >> 4;     // 0: even edge of pair, 1: odd edge
    int hl   = lane & 15;     // 16B slot within the row

    #pragma unroll
    for (int j = 0; j < EPW; j += 2) {
        int e = j + half;                              // edge for this half-warp
        int s = __shfl_sync(0xffffffffu, idx, e);      // src
        int d = __shfl_sync(0xffffffffu, idx, 16 + e); // dst
        uint4 raw = __ldg(&xh4[(size_t)s * 16 + hl]);  // 8 halves
        __half* p = aggh + (size_t)d * D + hl * 8;
        asm volatile("red.global.add.noftz.v4.f16x2 [%0], {%1, %2, %3, %4};"
                     :: "l"(p), "r"(raw.x), "r"(raw.y), "r"(raw.z), "r"(raw.w)
                     : "memory");
    }
}

// ---------------------------------------------------------------------------
// 2) epilogue: out = relu(scale*x + agg_fp16), re-zero agg, per-batch pooled
//    sums with run-length compression (batch sorted). One warp per 16 rows.
// ---------------------------------------------------------------------------
#define EPI_ROWS 16

__global__ void __launch_bounds__(256) k_epilogue(const float* __restrict__ x,
                                                  const float* __restrict__ eps,
                                                  const int* __restrict__ batch,
                                                  float* __restrict__ out) {
    int warp = (blockIdx.x * blockDim.x + threadIdx.x) >> 5;
    int lane = threadIdx.x & 31;
    int r0 = warp * EPI_ROWS;
    if (r0 >= N_NODES) return;
    int r1 = r0 + EPI_ROWS; if (r1 > N_NODES) r1 = N_NODES;

    float scale = 1.0f + eps[0];
    uint2* aggh2 = reinterpret_cast<uint2*>(g_aggh);   // 4 halves per lane-slot
    const float4* x4 = reinterpret_cast<const float4*>(x);
    float4* out4 = reinterpret_cast<float4*>(out);
    const float4 zero4 = make_float4(0.f, 0.f, 0.f, 0.f);

    float4 acc = zero4;
    int cnt = 0;
    int cur = batch[r0];

    for (int r = r0; r < r1; r++) {
        size_t idx = (size_t)r * 32 + lane;
        uint2 araw = __ldcg(&aggh2[idx]);
        half2 ah0 = *reinterpret_cast<half2*>(&araw.x);
        half2 ah1 = *reinterpret_cast<half2*>(&araw.y);
        float2 a0 = __half22float2(ah0);
        float2 a1 = __half22float2(ah1);
        float4 xv = x4[idx];
        float4 v;
        v.x = fmaxf(fmaf(xv.x, scale, a0.x), 0.f);
        v.y = fmaxf(fmaf(xv.y, scale, a0.y), 0.f);
        v.z = fmaxf(fmaf(xv.z, scale, a1.x), 0.f);
        v.w = fmaxf(fmaf(xv.w, scale, a1.y), 0.f);
        out4[idx] = v;
        aggh2[idx] = make_uint2(0u, 0u);   // self-restore (fp16 zero = 0 bits)

        int b = batch[r];
        if (b != cur) {
            float* p = &g_S[cur * D + lane * 4];
            asm volatile("red.global.add.v4.f32 [%0], {%1, %2, %3, %4};"
                         :: "l"(p), "f"(acc.x), "f"(acc.y), "f"(acc.z), "f"(acc.w)
                         : "memory");
            if (lane == 0) atomicAdd(&g_cnt[cur], (float)cnt);
            cur = b; acc = zero4; cnt = 0;
        }
        acc.x += v.x; acc.y += v.y; acc.z += v.z; acc.w += v.w;
        cnt++;
    }
    {
        float* p = &g_S[cur * D + lane * 4];
        asm volatile("red.global.add.v4.f32 [%0], {%1, %2, %3, %4};"
                     :: "l"(p), "f"(acc.x), "f"(acc.y), "f"(acc.z), "f"(acc.w)
                     : "memory");
        if (lane == 0) atomicAdd(&g_cnt[cur], (float)cnt);
    }
}

// ---------------------------------------------------------------------------
// 3) pooled2[b] = S[b] @ W + cnt[b]*bias. k-split across 8 y-threads for
//    latency hiding (1024 thr/block), smem partial reduce. Re-zeroes g_S/g_cnt.
// ---------------------------------------------------------------------------
__global__ void __launch_bounds__(1024) k_pool(const float* __restrict__ W,
                                               const float* __restrict__ bias,
                                               float* __restrict__ out2) {
    int b  = blockIdx.x;      // 0..63
    int j  = threadIdx.x;     // 0..127 output column
    int kk = threadIdx.y;     // 0..7   k-chunk
    __shared__ float s[D];
    __shared__ float partial[8][D];
    __shared__ float cntf;

    int t = kk * 128 + j;
    if (t < D) { s[t] = g_S[b * D + t]; g_S[b * D + t] = 0.0f; }
    if (t == 0) { cntf = g_cnt[b]; g_cnt[b] = 0.0f; }
    __syncthreads();

    float a = 0.f;
    #pragma unroll
    for (int k = kk * 16; k < kk * 16 + 16; k++)
        a = fmaf(s[k], __ldg(&W[k * D + j]), a);
    partial[kk][j] = a;
    __syncthreads();

    if (kk == 0) {
        float sum = cntf * bias[j];
        #pragma unroll
        for (int i = 0; i < 8; i++) sum += partial[i][j];
        out2[b * D + j] = sum;
    }
}

// ---------------------------------------------------------------------------
// launch: x, eps, W_pred, b_pred, edge_index, batch -> out | pooled2
// ---------------------------------------------------------------------------
extern "C" void kernel_launch(void* const* d_in, const int* in_sizes, int n_in,
                              void* d_out, int out_size) {
    const float* x     = (const float*)d_in[0];
    const float* eps   = (const float*)d_in[1];
    const float* Wp    = (const float*)d_in[2];
    const float* bp    = (const float*)d_in[3];
    const int*   ei    = (const int*)d_in[4];
    const int*   batch = (const int*)d_in[5];

    float* out  = (float*)d_out;
    float* out2 = out + (size_t)N_NODES * D;

    // fp16 copy of x
    {
        int total4 = N_NODES * D / 4;
        k_convert<<<(total4 + 255) / 256, 256>>>(x);
    }

    // edge scatter: one warp per EPW edges, fp16 v4 REDs
    {
        int warps = (N_EDGES + EPW - 1) / EPW;               // 50000
        int blocks = (warps * 32 + 255) / 256;               // 6250
        k_edges<<<blocks, 256>>>(ei);
    }

    // epilogue: relu + out + agg re-zero + batch partial sums
    {
        int warps = (N_NODES + EPI_ROWS - 1) / EPI_ROWS;     // 3125
        int blocks = (warps * 32 + 255) / 256;               // 391
        k_epilogue<<<blocks, 256>>>(x, eps, batch, out);
    }

    // pooled GEMM (k-split)
    {
        dim3 blk(128, 8);
        k_pool<<<NBATCH, blk>>>(Wp, bp, out2);
    }
}

// round 17
// speedup vs baseline: 2.7139x; 1.0731x over previous
#include <cuda_runtime.h>
#include <cuda_fp16.h>

#define N_NODES 50000
#define N_EDGES 800000
#define D 128
#define NBATCH 64
#define EPW 16                 // edges per warp (proven best shape)

// Device scratch (allocation-free, self-restoring across graph replays).
__device__ unsigned int g_aggh[N_NODES * D / 2]; // fp16 neighbor sums (re-zeroed by epilogue)
__device__ unsigned int g_xh[N_NODES * D / 2];   // x in fp16
__device__ float        g_S[NBATCH * D];         // pooled sums (zeroed by k_convert)
__device__ float        g_cnt[NBATCH];           // batch counts (zeroed by k_convert)

#define GRIDDEP_WAIT() asm volatile("griddepcontrol.wait;" ::: "memory")

// ---------------------------------------------------------------------------
// 0) convert x -> fp16 copy; zero pooling accumulators for this replay
//    (runs before epilogue's REDs; pool of the PREVIOUS replay already read them)
// ---------------------------------------------------------------------------
__global__ void k_convert(const float* __restrict__ x) {
    int i = blockIdx.x * blockDim.x + threadIdx.x;   // one float4 -> 2 half2
    const int total4 = N_NODES * D / 4;
    if (i < NBATCH * D) g_S[i] = 0.0f;
    if (i < NBATCH)     g_cnt[i] = 0.0f;
    if (i >= total4) return;
    float4 v = __ldcs(&reinterpret_cast<const float4*>(x)[i]);
    half2 h0 = __floats2half2_rn(v.x, v.y);
    half2 h1 = __floats2half2_rn(v.z, v.w);
    uint2 packed;
    packed.x = *reinterpret_cast<unsigned int*>(&h0);
    packed.y = *reinterpret_cast<unsigned int*>(&h1);
    reinterpret_cast<uint2*>(g_xh)[i] = packed;
}

// ---------------------------------------------------------------------------
// 1) edge scatter: one warp per 16 edges; two edges per iteration (half-warp
//    each), fixed unroll of 8. 16B fp16 gather -> fire-and-forget
//    red.global.add.noftz.v4.f16x2 (8 halves per lane).
// ---------------------------------------------------------------------------
__global__ void __launch_bounds__(256) k_edges(const int* __restrict__ ei) {
    GRIDDEP_WAIT();
    int warp = (blockIdx.x * blockDim.x + threadIdx.x) >> 5;
    int lane = threadIdx.x & 31;
    long long base = (long long)warp * EPW;
    if (base >= N_EDGES) return;

    int idx = (lane < EPW) ? __ldg(&ei[base + lane])
                           : __ldg(&ei[N_EDGES + base + (lane - EPW)]);

    const uint4* xh4 = reinterpret_cast<const uint4*>(g_xh);  // 16 uint4 per row
    __half* aggh = reinterpret_cast<__half*>(g_aggh);

    int half = lane >> 4;     // which edge of the pair
    int hl   = lane & 15;     // 16B slot within the row

    #pragma unroll
    for (int j = 0; j < EPW; j += 2) {
        int e = j + half;
        int s = __shfl_sync(0xffffffffu, idx, e);
        int d = __shfl_sync(0xffffffffu, idx, 16 + e);
        uint4 raw = __ldg(&xh4[(size_t)s * 16 + hl]);  // 8 halves
        __half* p = aggh + (size_t)d * D + hl * 8;
        asm volatile("red.global.add.noftz.v4.f16x2 [%0], {%1, %2, %3, %4};"
                     :: "l"(p), "r"(raw.x), "r"(raw.y), "r"(raw.z), "r"(raw.w)
                     : "memory");
    }
}

// ---------------------------------------------------------------------------
// 2) epilogue: out = relu(scale*x + agg_fp16), re-zero agg, per-batch pooled
//    sums with run-length compression (batch sorted). One warp per 16 rows.
// ---------------------------------------------------------------------------
#define EPI_ROWS 16

__global__ void __launch_bounds__(256) k_epilogue(const float* __restrict__ x,
                                                  const float* __restrict__ eps,
                                                  const int* __restrict__ batch,
                                                  float* __restrict__ out) {
    GRIDDEP_WAIT();
    int warp = (blockIdx.x * blockDim.x + threadIdx.x) >> 5;
    int lane = threadIdx.x & 31;
    int r0 = warp * EPI_ROWS;
    if (r0 >= N_NODES) return;
    int r1 = r0 + EPI_ROWS; if (r1 > N_NODES) r1 = N_NODES;

    float scale = 1.0f + eps[0];
    uint2* aggh2 = reinterpret_cast<uint2*>(g_aggh);
    const float4* x4 = reinterpret_cast<const float4*>(x);
    float4* out4 = reinterpret_cast<float4*>(out);
    const float4 zero4 = make_float4(0.f, 0.f, 0.f, 0.f);

    float4 acc = zero4;
    int cnt = 0;
    int cur = batch[r0];

    for (int r = r0; r < r1; r++) {
        size_t idx = (size_t)r * 32 + lane;
        uint2 araw = __ldcg(&aggh2[idx]);
        half2 ah0 = *reinterpret_cast<half2*>(&araw.x);
        half2 ah1 = *reinterpret_cast<half2*>(&araw.y);
        float2 a0 = __half22float2(ah0);
        float2 a1 = __half22float2(ah1);
        float4 xv = x4[idx];
        float4 v;
        v.x = fmaxf(fmaf(xv.x, scale, a0.x), 0.f);
        v.y = fmaxf(fmaf(xv.y, scale, a0.y), 0.f);
        v.z = fmaxf(fmaf(xv.z, scale, a1.x), 0.f);
        v.w = fmaxf(fmaf(xv.w, scale, a1.y), 0.f);
        out4[idx] = v;
        aggh2[idx] = make_uint2(0u, 0u);   // self-restore

        int b = batch[r];
        if (b != cur) {
            float* p = &g_S[cur * D + lane * 4];
            asm volatile("red.global.add.v4.f32 [%0], {%1, %2, %3, %4};"
                         :: "l"(p), "f"(acc.x), "f"(acc.y), "f"(acc.z), "f"(acc.w)
                         : "memory");
            if (lane == 0) atomicAdd(&g_cnt[cur], (float)cnt);
            cur = b; acc = zero4; cnt = 0;
        }
        acc.x += v.x; acc.y += v.y; acc.z += v.z; acc.w += v.w;
        cnt++;
    }
    {
        float* p = &g_S[cur * D + lane * 4];
        asm volatile("red.global.add.v4.f32 [%0], {%1, %2, %3, %4};"
                     :: "l"(p), "f"(acc.x), "f"(acc.y), "f"(acc.z), "f"(acc.w)
                     : "memory");
        if (lane == 0) atomicAdd(&g_cnt[cur], (float)cnt);
    }
}

// ---------------------------------------------------------------------------
// 3) pooled2[b] = S[b] @ W + cnt[b]*bias. Grid (64 b, 4 col-chunks) = 256
//    blocks, 128 thr: tid = (kk 0..3) x (j32 0..31); coalesced W loads.
//    No zeroing here (k_convert owns it).
// ---------------------------------------------------------------------------
__global__ void __launch_bounds__(128) k_pool(const float* __restrict__ W,
                                              const float* __restrict__ bias,
                                              float* __restrict__ out2) {
    GRIDDEP_WAIT();
    int b     = blockIdx.x;             // 0..63
    int jbase = blockIdx.y * 32;        // 0,32,64,96
    int j32   = threadIdx.x & 31;
    int kk    = threadIdx.x >> 5;       // 0..3
    __shared__ float s[D];
    __shared__ float partial[4][32];
    __shared__ float cntf;

    s[threadIdx.x] = g_S[b * D + threadIdx.x];        // 128 threads, full row
    if (threadIdx.x == 0) cntf = g_cnt[b];
    __syncthreads();

    float a = 0.f;
    #pragma unroll
    for (int k = kk * 32; k < kk * 32 + 32; k++)
        a = fmaf(s[k], __ldg(&W[k * D + jbase + j32]), a);
    partial[kk][j32] = a;
    __syncthreads();

    if (kk == 0) {
        float sum = cntf * bias[jbase + j32]
                  + ((partial[0][j32] + partial[1][j32])
                   + (partial[2][j32] + partial[3][j32]));
        out2[b * D + jbase + j32] = sum;
    }
}

// ---------------------------------------------------------------------------
// launch: x, eps, W_pred, b_pred, edge_index, batch -> out | pooled2
// PDL: edges/epilogue/pool launched with programmatic stream serialization;
// each begins with griddepcontrol.wait (upstream trigger implicit at finish).
// ---------------------------------------------------------------------------
static void launch_pdl(const void* func, dim3 grid, dim3 block,
                       void** args) {
    cudaLaunchConfig_t cfg = {};
    cfg.gridDim = grid;
    cfg.blockDim = block;
    cfg.dynamicSmemBytes = 0;
    cfg.stream = 0;
    cudaLaunchAttribute attr[1];
    attr[0].id = cudaLaunchAttributeProgrammaticStreamSerialization;
    attr[0].val.programmaticStreamSerializationAllowed = 1;
    cfg.attrs = attr;
    cfg.numAttrs = 1;
    cudaLaunchKernelExC(&cfg, func, args);
}

extern "C" void kernel_launch(void* const* d_in, const int* in_sizes, int n_in,
                              void* d_out, int out_size) {
    const float* x     = (const float*)d_in[0];
    const float* eps   = (const float*)d_in[1];
    const float* Wp    = (const float*)d_in[2];
    const float* bp    = (const float*)d_in[3];
    const int*   ei    = (const int*)d_in[4];
    const int*   batch = (const int*)d_in[5];

    float* out  = (float*)d_out;
    float* out2 = out + (size_t)N_NODES * D;

    // 0) fp16 copy of x + zero pooled accumulators
    {
        int total4 = N_NODES * D / 4;
        k_convert<<<(total4 + 255) / 256, 256>>>(x);
    }

    // 1) edge scatter (PDL after convert)
    {
        int warps = (N_EDGES + EPW - 1) / EPW;               // 50000
        int blocks = (warps * 32 + 255) / 256;               // 6250
        void* args[] = { (void*)&ei };
        launch_pdl((const void*)k_edges, dim3(blocks), dim3(256), args);
    }

    // 2) epilogue (PDL after edges)
    {
        int warps = (N_NODES + EPI_ROWS - 1) / EPI_ROWS;     // 3125
        int blocks = (warps * 32 + 255) / 256;               // 391
        void* args[] = { (void*)&x, (void*)&eps, (void*)&batch, (void*)&out };
        launch_pdl((const void*)k_epilogue, dim3(blocks), dim3(256), args);
    }

    // 3) pooled GEMM (PDL after epilogue)
    {
        void* args[] = { (void*)&Wp, (void*)&bp, (void*)&out2 };
        launch_pdl((const void*)k_pool, dim3(NBATCH, 4), dim3(128), args);
    }
}